// round 7
// baseline (speedup 1.0000x reference)
#include <cuda_runtime.h>
#include <cstdint>

#define B_ 16
#define N_ 2048
#define F_ 128
#define C1 32
#define TM 64            // rows per CTA tile
#define KT 32
#define PA 36            // As smem pitch (floats)
#define PT 40            // Ts smem pitch (uints)
#define NTILES (N_ / TM) // 32

// Scratch (static device globals — no allocation allowed)
__device__ uint32_t g_Tt[B_ * N_ * C1];      // T1 = X@W1 as tf32 bits
__device__ uint32_t g_T2t[B_ * N_ * C1];     // T2 = elu(A@T1+b1)@W2 as tf32 bits
__device__ uint32_t g_W1t[F_ * C1];          // W1 as tf32 bits
__device__ float    g_poolpart[B_ * NTILES * C1];

__device__ __forceinline__ float elu_f(float x) {
    return x > 0.f ? x : (__expf(x) - 1.f);
}

__device__ __forceinline__ uint32_t f2tf(float f) {
    uint32_t r;
    asm("cvt.rna.tf32.f32 %0, %1;" : "=r"(r) : "f"(f));
    return r;
}

__device__ __forceinline__ void cp16(void* dst, const void* src) {
    uint32_t d = (uint32_t)__cvta_generic_to_shared(dst);
    asm volatile("cp.async.cg.shared.global [%0], [%1], 16;\n" :: "r"(d), "l"(src));
}

__device__ __forceinline__ void mma_tf32(float c[4], uint32_t a0, uint32_t a1,
                                         uint32_t a2, uint32_t a3,
                                         uint32_t b0, uint32_t b1) {
    asm volatile(
        "mma.sync.aligned.m16n8k8.row.col.f32.tf32.tf32.f32 "
        "{%0,%1,%2,%3}, {%4,%5,%6,%7}, {%8,%9}, {%0,%1,%2,%3};"
        : "+f"(c[0]), "+f"(c[1]), "+f"(c[2]), "+f"(c[3])
        : "r"(a0), "r"(a1), "r"(a2), "r"(a3), "r"(b0), "r"(b1));
}

// ---------------------------------------------------------------------------
// K0: convert W1 to tf32 bits (tiny)
// ---------------------------------------------------------------------------
__global__ void k_prep(const float* __restrict__ W1) {
    int tid = threadIdx.x;
    for (int i = tid; i < F_ * C1; i += 256) g_W1t[i] = f2tf(W1[i]);
}

// ---------------------------------------------------------------------------
// Unified TF32 tensor-core GEMM, 64x32 tile per CTA, 128 threads (4 warps).
//   MODE 0: XW1       A=x [32768,128], K=128 -> g_Tt (tf32)
//   MODE 1: AGG1+HW2  A=a[b], K=2048, B=g_Tt  -> T2 -> g_T2t (separate buffer!)
//   MODE 3: AGG2+POOL A=a[b], K=2048, B=g_T2t -> poolpart = colsum(elu(.+b2))
// cp.async 2-stage, all-resident grid (512 CTAs, ~6 CTAs/SM).
// ---------------------------------------------------------------------------
template <int MODE>
__global__ void __launch_bounds__(128, 6)
k_gemm(const float* __restrict__ Abase, const float* __restrict__ bias,
       const float* __restrict__ W2f) {
    constexpr bool AGG = (MODE != 0);
    constexpr int LDA = AGG ? N_ : F_;
    constexpr int NKT = LDA / KT;

    __shared__ __align__(16) float As[2][TM][PA];
    __shared__ __align__(16) uint32_t Ts[2][KT][PT];
    __shared__ float Ws[C1][C1];     // W2 (MODE 1)
    __shared__ float red[4][C1];     // pool partials (MODE 3)

    const int tid = threadIdx.x;            // 128
    const int b = AGG ? blockIdx.y : 0;
    const int t0 = blockIdx.x * TM;

    const float* A = Abase + (AGG ? ((size_t)b * N_ + t0) * N_ : (size_t)t0 * LDA);
    const uint32_t* Bp = AGG ? (MODE == 1 ? g_Tt : g_T2t) + (size_t)b * N_ * C1
                             : g_W1t;

    const int wid = tid >> 5;               // 0..3 -> rows wid*16..+15
    const int lane = tid & 31;
    const int g = lane >> 2;                // 0..7
    const int q = lane & 3;                 // 0..3
    const int rw = wid * 16;

    const int lar = tid >> 3;               // 0..15
    const int lac = (tid & 7) * 4;

    const float* asrc0 = A + (size_t)lar * LDA + lac;
    const uint32_t* bsrc = Bp + lar * C1 + lac;

    if (MODE == 1) {   // stage W2 into smem (consumed only after main-loop syncs)
        for (int i = tid; i < C1 * C1; i += 128) Ws[i >> 5][i & 31] = W2f[i];
    }

    float acc[4][4];
#pragma unroll
    for (int j = 0; j < 4; j++)
#pragma unroll
        for (int i = 0; i < 4; i++) acc[j][i] = 0.f;

    // prologue: stage 0
#pragma unroll
    for (int j = 0; j < 4; j++)
        cp16(&As[0][lar + j * 16][lac], asrc0 + (size_t)j * 16 * LDA);
    cp16(&Ts[0][lar][lac], bsrc);
    cp16(&Ts[0][lar + 16][lac], bsrc + 16 * C1);
    asm volatile("cp.async.commit_group;\n");

    for (int kt = 0; kt < NKT; kt++) {
        const int cur = kt & 1;
        if (kt + 1 < NKT) {
            const int nxt = cur ^ 1;
            const float* an = asrc0 + (kt + 1) * KT;
            const uint32_t* bn = bsrc + (kt + 1) * KT * C1;
#pragma unroll
            for (int j = 0; j < 4; j++)
                cp16(&As[nxt][lar + j * 16][lac], an + (size_t)j * 16 * LDA);
            cp16(&Ts[nxt][lar][lac], bn);
            cp16(&Ts[nxt][lar + 16][lac], bn + 16 * C1);
            asm volatile("cp.async.commit_group;\n");
            asm volatile("cp.async.wait_group 1;\n");
        } else {
            asm volatile("cp.async.wait_group 0;\n");
        }
        __syncthreads();

#pragma unroll
        for (int k8 = 0; k8 < KT / 8; k8++) {
            const int kk = k8 * 8;
            uint32_t A0 = f2tf(As[cur][rw + g][kk + q]);
            uint32_t A1 = f2tf(As[cur][rw + g + 8][kk + q]);
            uint32_t A2 = f2tf(As[cur][rw + g][kk + q + 4]);
            uint32_t A3 = f2tf(As[cur][rw + g + 8][kk + q + 4]);
#pragma unroll
            for (int j = 0; j < 4; j++) {
                uint32_t B0 = Ts[cur][kk + q][8 * j + g];
                uint32_t B1 = Ts[cur][kk + q + 4][8 * j + g];
                mma_tf32(acc[j], A0, A1, A2, A3, B0, B1);
            }
        }
        __syncthreads();
    }

    if (MODE == 0) {
        // store tf32 bits to g_Tt
#pragma unroll
        for (int j = 0; j < 4; j++) {
            const int col = 8 * j + 2 * q;
            const size_t r0 = ((size_t)t0 + rw + g) * C1 + col;
            const size_t r1 = r0 + 8 * C1;
            *(uint2*)&g_Tt[r0] = make_uint2(f2tf(acc[j][0]), f2tf(acc[j][1]));
            *(uint2*)&g_Tt[r1] = make_uint2(f2tf(acc[j][2]), f2tf(acc[j][3]));
        }
    } else if (MODE == 1) {
        // H tile = elu(acc + b1) -> smem (reuse As[0]); then T2 = H @ W2 (fp32)
        float (*Hs)[PA] = As[0];
#pragma unroll
        for (int j = 0; j < 4; j++) {
            const int col = 8 * j + 2 * q;
            const float bc0 = bias[col], bc1 = bias[col + 1];
            *(float2*)&Hs[rw + g][col] =
                make_float2(elu_f(acc[j][0] + bc0), elu_f(acc[j][1] + bc1));
            *(float2*)&Hs[rw + g + 8][col] =
                make_float2(elu_f(acc[j][2] + bc0), elu_f(acc[j][3] + bc1));
        }
        __syncthreads();
        // each thread: one row r = tid>>1, 16 cols (half = (tid&1)*16)
        const int r = tid >> 1;
        const int ch = (tid & 1) * 16;
        float t2[16];
#pragma unroll
        for (int c = 0; c < 16; c++) t2[c] = 0.f;
#pragma unroll
        for (int k = 0; k < C1; k++) {
            const float h = Hs[r][k];
#pragma unroll
            for (int c = 0; c < 16; c++) t2[c] += h * Ws[k][ch + c];
        }
        uint32_t* op = &g_T2t[((size_t)b * N_ + t0 + r) * C1 + ch];
#pragma unroll
        for (int c4 = 0; c4 < 4; c4++) {
            uint4 v = make_uint4(f2tf(t2[c4 * 4]), f2tf(t2[c4 * 4 + 1]),
                                 f2tf(t2[c4 * 4 + 2]), f2tf(t2[c4 * 4 + 3]));
            *(uint4*)&op[c4 * 4] = v;
        }
    } else {
        // pool: colsum of elu(acc + b2)
#pragma unroll
        for (int j = 0; j < 4; j++) {
            const int col = 8 * j + 2 * q;
            const float bc0 = bias[col], bc1 = bias[col + 1];
            float s0 = elu_f(acc[j][0] + bc0) + elu_f(acc[j][2] + bc0);
            float s1 = elu_f(acc[j][1] + bc1) + elu_f(acc[j][3] + bc1);
#pragma unroll
            for (int m = 4; m < 32; m <<= 1) {
                s0 += __shfl_xor_sync(0xffffffffu, s0, m);
                s1 += __shfl_xor_sync(0xffffffffu, s1, m);
            }
            if (g == 0) {
                red[wid][col] = s0;
                red[wid][col + 1] = s1;
            }
        }
        __syncthreads();
        if (tid < C1) {
            float s = red[0][tid] + red[1][tid] + red[2][tid] + red[3][tid];
            g_poolpart[((size_t)b * NTILES + blockIdx.x) * C1 + tid] = s;
        }
    }
}

// ---------------------------------------------------------------------------
// K5: head, one block per batch. Deterministic fixed-order reductions.
// ---------------------------------------------------------------------------
__global__ void k_head(const float* __restrict__ wf1, const float* __restrict__ bf1,
                       const float* __restrict__ wf2, const float* __restrict__ bf2,
                       float* __restrict__ out) {
    __shared__ float ps[C1];
    __shared__ float srd[512];
    const int b = blockIdx.x;
    const int tid = threadIdx.x;   // 512

    if (tid < C1) {
        float s = 0.f;
#pragma unroll
        for (int t = 0; t < NTILES; t++)
            s += g_poolpart[((size_t)b * NTILES + t) * C1 + tid];
        ps[tid] = s;
    }
    __syncthreads();

    float z = bf1[tid];
#pragma unroll
    for (int k = 0; k < C1; k++)
        z += ps[k] * wf1[k * 512 + tid];
    srd[tid] = fmaxf(z, 0.f) * wf2[tid];
    __syncthreads();
    for (int s = 256; s > 0; s >>= 1) {
        if (tid < s) srd[tid] += srd[tid + s];
        __syncthreads();
    }
    if (tid == 0) out[b] = 1.f / (1.f + __expf(-(srd[0] + bf2[0])));
}

// ---------------------------------------------------------------------------
extern "C" void kernel_launch(void* const* d_in, const int* in_sizes, int n_in,
                              void* d_out, int out_size) {
    const float* x   = (const float*)d_in[0];
    const float* a   = (const float*)d_in[1];
    const float* w1  = (const float*)d_in[2];
    const float* b1  = (const float*)d_in[3];
    const float* w2  = (const float*)d_in[4];
    const float* b2  = (const float*)d_in[5];
    const float* wf1 = (const float*)d_in[6];
    const float* bf1 = (const float*)d_in[7];
    const float* wf2 = (const float*)d_in[8];
    const float* bf2 = (const float*)d_in[9];
    float* out = (float*)d_out;

    (void)in_sizes; (void)n_in; (void)out_size;

    cudaFuncSetAttribute(k_gemm<0>, cudaFuncAttributePreferredSharedMemoryCarveout, 100);
    cudaFuncSetAttribute(k_gemm<1>, cudaFuncAttributePreferredSharedMemoryCarveout, 100);
    cudaFuncSetAttribute(k_gemm<3>, cudaFuncAttributePreferredSharedMemoryCarveout, 100);

    dim3 gagg(NTILES, B_);   // 32 x 16 = 512 CTAs

    k_prep<<<1, 256>>>(w1);                                   // W1 -> tf32
    k_gemm<0><<<(B_ * N_) / TM, 128>>>(x, nullptr, nullptr);  // g_Tt = X @ W1
    k_gemm<1><<<gagg, 128>>>(a, b1, w2);                      // g_T2t = elu(A@T+b1)@W2
    k_gemm<3><<<gagg, 128>>>(a, b2, nullptr);                 // poolpart
    k_head<<<B_, 512>>>(wf1, bf1, wf2, bf2, out);             // FC head -> out[16]
}